// round 16
// baseline (speedup 1.0000x reference)
#include <cuda_runtime.h>
#include <cuda_fp16.h>
#include <cstdint>
#include <cstddef>

// ---------------------------------------------------------------------------
// ExpertChoice via mma.sync fp16 GEMMs, all 1-term.
// R16: gemm_t1 redesigned: CTA 128x128 with 128 threads (4 warps of 64x64),
//      2 CTAs/SM. Theory: t1 was smem-BW co-critical (ldsm 192 B/MMA, ~90% of
//      MMA time); 64x64 warps give 128 B/MMA (~65%). R14's failure was the
//      1-CTA/SM occupancy collapse, not warp width — this keeps 2 CTAs/SM.
//      + er single fp16 (calibrated +2.8e-4 quadrature -> ~7.3e-4).
// Error ledger: 6.76e-4 measured (R15).
// ---------------------------------------------------------------------------

#define Bq   1024
#define Nn   8
#define Dd   768
#define Ee   8
#define Kk   4
#define KD   3072
#define ND   6144
#define NC   1000
#define NCpad 1024

// ----- scratch (__device__ globals; no allocation allowed) ------------------
__device__ int   g_I[Bq * Nn * Kk];

__device__ __align__(16) __half g_W1h[(size_t)Ee * KD * KD];
__device__ __align__(16) __half g_W2h[(size_t)Ee * KD * KD];
__device__ __align__(16) __half g_sw1h[(size_t)ND * ND];
__device__ __align__(16) __half g_ch1h[(size_t)KD * KD];
__device__ __align__(16) __half g_ch2h[(size_t)NCpad * KD];

__device__ __align__(16) __half g_selh[(size_t)Ee * Bq * KD];
__device__ __align__(16) __half g_hh  [(size_t)Ee * Bq * KD];
__device__ __align__(16) __half g_erh[(size_t)Ee * Bq * KD];
__device__ __align__(16) __half g_xh[(size_t)Bq * ND];
__device__ float g_hw[(size_t)Bq * ND];
__device__ float g_w [Bq * Ee];
__device__ __align__(16) __half g_wsh[(size_t)Bq * KD];
__device__ __align__(16) __half g_hhh[(size_t)Bq * KD];

// ----- small helpers ---------------------------------------------------------
__device__ __forceinline__ float gelu_exact(float v) {
    return 0.5f * v * (1.0f + erff(v * 0.70710678118654752f));
}
__device__ __forceinline__ uint32_t smem_u32(const void* p) {
    uint32_t a;
    asm("{ .reg .u64 t; cvta.to.shared.u64 t, %1; cvt.u32.u64 %0, t; }" : "=r"(a) : "l"(p));
    return a;
}
__device__ __forceinline__ void cp_async16(uint32_t dst, const void* src) {
    asm volatile("cp.async.cg.shared.global [%0], [%1], 16;" :: "r"(dst), "l"(src));
}
__device__ __forceinline__ void cp_commit() {
    asm volatile("cp.async.commit_group;" ::: "memory");
}
template <int N>
__device__ __forceinline__ void cp_wait() {
    asm volatile("cp.async.wait_group %0;" :: "n"(N) : "memory");
}
__device__ __forceinline__ void ldsm_x4(uint32_t& r0, uint32_t& r1, uint32_t& r2,
                                        uint32_t& r3, uint32_t addr) {
    asm volatile("ldmatrix.sync.aligned.m8n8.x4.shared.b16 {%0,%1,%2,%3}, [%4];"
                 : "=r"(r0), "=r"(r1), "=r"(r2), "=r"(r3) : "r"(addr));
}
__device__ __forceinline__ void mma16816h(float* c, const uint32_t* a, const uint32_t* b) {
    asm volatile(
        "mma.sync.aligned.m16n8k16.row.col.f32.f16.f16.f32 "
        "{%0,%1,%2,%3}, {%4,%5,%6,%7}, {%8,%9}, {%0,%1,%2,%3};"
        : "+f"(c[0]), "+f"(c[1]), "+f"(c[2]), "+f"(c[3])
        : "r"(a[0]), "r"(a[1]), "r"(a[2]), "r"(a[3]), "r"(b[0]), "r"(b[1]));
}

// ----- router -----------------------------------------------------------------
__global__ void router_kernel(const float* __restrict__ x,
                              const float* __restrict__ emb,
                              int* __restrict__ I) {
    int gwarp = (blockIdx.x * blockDim.x + threadIdx.x) >> 5;
    int lane  = threadIdx.x & 31;
    if (gwarp >= Bq * Nn) return;
    int b = gwarp / Nn, n = gwarp % Nn;
    const float* xv = x + ((size_t)b * Nn + n) * Dd;
    float acc[Ee];
#pragma unroll
    for (int e = 0; e < Ee; e++) acc[e] = 0.f;
    for (int d = lane; d < Dd; d += 32) {
        float xd = xv[d];
#pragma unroll
        for (int e = 0; e < Ee; e++) acc[e] += xd * __ldg(&emb[e * Dd + d]);
    }
#pragma unroll
    for (int e = 0; e < Ee; e++)
#pragma unroll
        for (int off = 16; off; off >>= 1)
            acc[e] += __shfl_xor_sync(0xffffffffu, acc[e], off);
    if (lane == 0) {
        bool used[Ee] = {};
#pragma unroll
        for (int j = 0; j < Kk; j++) {
            int best = 0; float bv = -3.0e38f;
#pragma unroll
            for (int e = 0; e < Ee; e++)
                if (!used[e] && acc[e] > bv) { bv = acc[e]; best = e; }
            used[best] = true;
            I[((size_t)b * Nn + n) * Kk + j] = best;
        }
    }
}

// ----- gather -> single fp16 ----------------------------------------------------
__global__ void gather_half_kernel(const float* __restrict__ x,
                                   const int* __restrict__ I,
                                   __half* __restrict__ sh) {
    size_t idx = (size_t)blockIdx.x * blockDim.x + threadIdx.x;  // float4 index
    const size_t total = (size_t)Ee * Bq * KD / 4;
    if (idx >= total) return;
    int d4   = (int)(idx % (Dd / 4));
    size_t r = idx / (Dd / 4);
    int j = (int)(r % Kk); r /= Kk;
    int b = (int)(r % Bq);
    int e = (int)(r / Bq);
    int t = I[((size_t)b * Nn + e) * Kk + j];
    float4 v = reinterpret_cast<const float4*>(x)[((size_t)b * Nn + t) * (Dd / 4) + d4];
    __half2* oh = reinterpret_cast<__half2*>(sh + idx * 4);
    oh[0] = __halves2half2(__float2half_rn(v.x), __float2half_rn(v.y));
    oh[1] = __halves2half2(__float2half_rn(v.z), __float2half_rn(v.w));
}

__global__ void convert_half_kernel(const float* __restrict__ src,
                                    __half* __restrict__ dh, size_t n4) {
    size_t idx = (size_t)blockIdx.x * blockDim.x + threadIdx.x;
    if (idx >= n4) return;
    float4 v = reinterpret_cast<const float4*>(src)[idx];
    __half2* oh = reinterpret_cast<__half2*>(dh + idx * 4);
    oh[0] = __halves2half2(__float2half_rn(v.x), __float2half_rn(v.y));
    oh[1] = __halves2half2(__float2half_rn(v.z), __float2half_rn(v.w));
}

// ----- weight transpose -> single fp16 copy: Wt[n][k] = W[k][n] ----------------
__global__ __launch_bounds__(256)
void transpose_half_kernel(const float* __restrict__ W,
                           __half* __restrict__ Th,
                           int K, int N, size_t sW, size_t sT) {
    W  += (size_t)blockIdx.z * sW;
    Th += (size_t)blockIdx.z * sT;
    __shared__ float s[64][65];
    const int k0 = blockIdx.x * 64, n0 = blockIdx.y * 64;
    const int id = threadIdx.x;
#pragma unroll
    for (int it = 0; it < 16; it++) {
        int row = it * 4 + (id >> 6);
        int col = id & 63;
        int n = n0 + col;
        s[row][col] = (n < N) ? W[(size_t)(k0 + row) * N + n] : 0.f;
    }
    __syncthreads();
#pragma unroll
    for (int it = 0; it < 8; it++) {
        int n = it * 8 + (id >> 5);
        int c = id & 31;
        float v0 = s[2 * c][n], v1 = s[2 * c + 1][n];
        size_t o = ((size_t)(n0 + n) * K + k0 + 2 * c) >> 1;
        reinterpret_cast<__half2*>(Th)[o] =
            __halves2half2(__float2half_rn(v0), __float2half_rn(v1));
    }
}

// ----- GEMM config ---------------------------------------------------------------
#define BKc   32
#define ROW_B 64
#define TILE_B (128 * ROW_B)              // 8192 B per matrix tile
#define STAGE1_B (2 * TILE_B)             // A, B
#define NSTG1 4
#define GEMM1_SMEM (NSTG1 * STAGE1_B + 256)   // 65792 B; 2 CTAs/SM

// ----- 1-term GEMM: C = A*B^T + bias. 128x128 CTA tile, 128 threads,
//       4 warps of 64x64 (32 MMA per 8 ldsm per kk), 4-stage, pair barrier.
__global__ __launch_bounds__(128, 2)
void gemm_t1(const __half* __restrict__ Ah,
             const __half* __restrict__ Bh,
             const float* __restrict__ bias,
             float* __restrict__ Cf,
             __half* __restrict__ Ch, __half* __restrict__ Cl,
             int K, int Nact, int ldC, int act,
             size_t strA, size_t strB, size_t strBias, size_t strC) {
    extern __shared__ char smem_raw[];
    uint32_t sb = (smem_u32(smem_raw) + 127u) & ~127u;

    const int tid  = threadIdx.x;            // 0..127
    const int wid  = tid >> 5;                // 0..3
    const int lane = tid & 31;
    const int wm = (wid >> 1) * 64;           // 0 or 64
    const int wn = (wid & 1) * 64;            // 0 or 64
    const int m0 = blockIdx.x * 128;
    const int n0 = blockIdx.y * 128;
    const int z  = blockIdx.z;

    Ah += (size_t)z * strA;
    Bh += (size_t)z * strB;
    bias += (size_t)z * strBias;
    if (Cf) Cf += (size_t)z * strC;
    if (Ch) Ch += (size_t)z * strC;
    if (Cl) Cl += (size_t)z * strC;

    // cp.async pattern (128 threads): per tile 512 chunks of 16B, 4/thread
    const int lrow = tid >> 2;                // 0..31
    const int ck   = tid & 3;
    const __half* baseA = Ah + (size_t)m0 * K;
    const __half* baseB = Bh + (size_t)n0 * K;

    float acc[4][8][4];
#pragma unroll
    for (int a = 0; a < 4; a++)
#pragma unroll
        for (int b = 0; b < 8; b++)
#pragma unroll
            for (int c = 0; c < 4; c++) acc[a][b][c] = 0.f;

    auto load_stage = [&](int buf, int k0) {
        const uint32_t stg = sb + (uint32_t)buf * STAGE1_B;
#pragma unroll
        for (int i = 0; i < 4; i++) {
            int row = i * 32 + lrow;
            uint32_t so = (uint32_t)(row * ROW_B + ((ck ^ ((row >> 1) & 3)) << 4));
            cp_async16(stg + so, baseA + (size_t)row * K + k0 + ck * 8);
            cp_async16(stg + TILE_B + so, baseB + (size_t)row * K + k0 + ck * 8);
        }
    };

    const int nsteps = K / BKc;   // even for all call sites (96 or 192)
    load_stage(0, 0);
    cp_commit();
    load_stage(1, BKc);
    cp_commit();

    const int grp = lane >> 3;
    const int lr  = lane & 7;
    const int a_row = ((grp & 1) << 3) + lr;
    const int a_ck  = grp >> 1;
    const int b_row = ((grp >> 1) << 3) + lr;
    const int b_ck  = grp & 1;
    const int swz_a = ((wm + a_row) >> 1) & 3;
    const int swz_b = ((wn + b_row) >> 1) & 3;
    const uint32_t a_base = (uint32_t)(wm + a_row) * ROW_B;
    const uint32_t b_base = (uint32_t)(wn + b_row) * ROW_B;

    auto compute_step = [&](int bufidx) {
        const uint32_t stg = sb + (uint32_t)bufidx * STAGE1_B;
        const uint32_t sAh = stg;
        const uint32_t sBh = stg + TILE_B;
#pragma unroll
        for (int kk = 0; kk < 2; kk++) {
            const uint32_t a_coff = (uint32_t)(((kk * 2 + a_ck) ^ swz_a) << 4);
            const uint32_t b_coff = (uint32_t)(((kk * 2 + b_ck) ^ swz_b) << 4);
            // all fragments upfront: 4 B-ldsm (8 nt), 4 A-ldsm (4 mt)
            uint32_t bh[8][2];
#pragma unroll
            for (int j = 0; j < 4; j++) {
                uint32_t boff = b_base + (uint32_t)(j * 16) * ROW_B + b_coff;
                ldsm_x4(bh[j * 2][0], bh[j * 2][1], bh[j * 2 + 1][0], bh[j * 2 + 1][1],
                        sBh + boff);
            }
            uint32_t ah[4][4];
#pragma unroll
            for (int mt = 0; mt < 4; mt++) {
                uint32_t aoff = a_base + (uint32_t)(mt * 16) * ROW_B + a_coff;
                ldsm_x4(ah[mt][0], ah[mt][1], ah[mt][2], ah[mt][3], sAh + aoff);
            }
#pragma unroll
            for (int mt = 0; mt < 4; mt++)
#pragma unroll
                for (int nt = 0; nt < 8; nt++)
                    mma16816h(acc[mt][nt], ah[mt], bh[nt]);
        }
    };

    // one barrier per pair of K-steps (NSTG1=4 >= lookahead 2 + 2)
    for (int s = 0; s < nsteps; s += 2) {
        cp_wait<0>();
        __syncthreads();
        if (s + 2 < nsteps) {
            load_stage((s + 2) & 3, (s + 2) * BKc);
            cp_commit();
            load_stage((s + 3) & 3, (s + 3) * BKc);
            cp_commit();
        }
        compute_step(s & 3);
        compute_step((s + 1) & 3);
    }

#pragma unroll
    for (int mt = 0; mt < 4; mt++) {
#pragma unroll
        for (int nt = 0; nt < 8; nt++) {
            int row = m0 + wm + mt * 16 + (lane >> 2);
            int col = n0 + wn + nt * 8 + ((lane & 3) << 1);
            if (col < Nact) {
                float bv0 = __ldg(&bias[col]);
                float bv1 = __ldg(&bias[col + 1]);
#pragma unroll
                for (int half_i = 0; half_i < 2; half_i++) {
                    int r = row + half_i * 8;
                    float v0 = acc[mt][nt][half_i * 2 + 0] + bv0;
                    float v1 = acc[mt][nt][half_i * 2 + 1] + bv1;
                    if (act) { v0 = gelu_exact(v0); v1 = gelu_exact(v1); }
                    size_t gidx = (size_t)r * ldC + col;
                    if (Cf) *reinterpret_cast<float2*>(Cf + gidx) = make_float2(v0, v1);
                    if (Ch)
                        *reinterpret_cast<__half2*>(Ch + gidx) =
                            __halves2half2(__float2half_rn(v0), __float2half_rn(v1));
                }
            }
        }
    }
    (void)Cl;
}

// ----- sum-weights fc2 (N=8) + softmax (fp32) ----------------------------------
__global__ void sw2_softmax_kernel(const float* __restrict__ hw,
                                   const float* __restrict__ swW2,
                                   const float* __restrict__ swb2,
                                   float* __restrict__ w) {
    int b = blockIdx.x;
    int lane = threadIdx.x & 31, warp = threadIdx.x >> 5;
    float acc[Ee];
#pragma unroll
    for (int e = 0; e < Ee; e++) acc[e] = 0.f;
    const float* a = hw + (size_t)b * ND;
    for (int k = threadIdx.x; k < ND; k += 256) {
        float av = a[k];
#pragma unroll
        for (int e = 0; e < Ee; e++) acc[e] += av * __ldg(&swW2[(size_t)k * Ee + e]);
    }
#pragma unroll
    for (int e = 0; e < Ee; e++)
#pragma unroll
        for (int off = 16; off; off >>= 1)
            acc[e] += __shfl_xor_sync(0xffffffffu, acc[e], off);
    __shared__ float sh[8][Ee];
    if (lane == 0)
#pragma unroll
        for (int e = 0; e < Ee; e++) sh[warp][e] = acc[e];
    __syncthreads();
    if (threadIdx.x == 0) {
        float v[Ee]; float mx = -3.0e38f;
#pragma unroll
        for (int e = 0; e < Ee; e++) {
            float s = swb2[e];
            for (int wi = 0; wi < 8; wi++) s += sh[wi][e];
            v[e] = s; mx = fmaxf(mx, s);
        }
        float den = 0.f;
#pragma unroll
        for (int e = 0; e < Ee; e++) { v[e] = __expf(v[e] - mx); den += v[e]; }
        float inv = 1.0f / den;
#pragma unroll
        for (int e = 0; e < Ee; e++) w[b * Ee + e] = v[e] * inv;
    }
}

// ----- weighted sum over experts (single fp16 er) -> single fp16 ws -------------
__global__ void wsum_half_kernel(const __half* __restrict__ erh,
                                 const float* __restrict__ w,
                                 __half* __restrict__ wsh) {
    size_t idx = (size_t)blockIdx.x * blockDim.x + threadIdx.x;  // group of 4 elems
    const size_t total = (size_t)Bq * KD / 4;
    if (idx >= total) return;
    int b = (int)(idx / (KD / 4));
    float s0 = 0.f, s1 = 0.f, s2 = 0.f, s3 = 0.f;
#pragma unroll
    for (int e = 0; e < Ee; e++) {
        float we = __ldg(&w[b * Ee + e]);
        size_t o = (size_t)e * (Bq * KD / 4) + idx;
        uint2 hp = reinterpret_cast<const uint2*>(erh)[o];
        __half2 h01 = *reinterpret_cast<__half2*>(&hp.x);
        __half2 h23 = *reinterpret_cast<__half2*>(&hp.y);
        s0 += we * __half2float(h01.x);
        s1 += we * __half2float(h01.y);
        s2 += we * __half2float(h23.x);
        s3 += we * __half2float(h23.y);
    }
    __half2* oh = reinterpret_cast<__half2*>(wsh + idx * 4);
    oh[0] = __halves2half2(__float2half_rn(s0), __float2half_rn(s1));
    oh[1] = __halves2half2(__float2half_rn(s2), __float2half_rn(s3));
}

// ------------------------------------------------------------------------------
extern "C" void kernel_launch(void* const* d_in, const int* in_sizes, int n_in,
                              void* d_out, int out_size) {
    const float* x    = (const float*)d_in[0];
    const float* emb  = (const float*)d_in[1];
    const float* W1   = (const float*)d_in[2];
    const float* b1   = (const float*)d_in[3];
    const float* W2   = (const float*)d_in[4];
    const float* b2   = (const float*)d_in[5];
    const float* swW1 = (const float*)d_in[6];
    const float* swb1 = (const float*)d_in[7];
    const float* swW2 = (const float*)d_in[8];
    const float* swb2 = (const float*)d_in[9];
    const float* chW1 = (const float*)d_in[10];
    const float* chb1 = (const float*)d_in[11];
    const float* chW2 = (const float*)d_in[12];
    const float* chb2 = (const float*)d_in[13];
    float* out = (float*)d_out;

    cudaFuncSetAttribute(gemm_t1, cudaFuncAttributeMaxDynamicSharedMemorySize, GEMM1_SMEM);

    int* I;
    __half *W1h, *W2h, *sw1h, *ch1h, *ch2h;
    __half *selh, *hh, *erh, *xh, *wsh, *hhh;
    float *hw, *w;
    cudaGetSymbolAddress((void**)&I,    g_I);
    cudaGetSymbolAddress((void**)&W1h,  g_W1h);
    cudaGetSymbolAddress((void**)&W2h,  g_W2h);
    cudaGetSymbolAddress((void**)&sw1h, g_sw1h);
    cudaGetSymbolAddress((void**)&ch1h, g_ch1h);
    cudaGetSymbolAddress((void**)&ch2h, g_ch2h);
    cudaGetSymbolAddress((void**)&selh, g_selh);
    cudaGetSymbolAddress((void**)&hh,   g_hh);
    cudaGetSymbolAddress((void**)&erh,  g_erh);
    cudaGetSymbolAddress((void**)&xh,   g_xh);
    cudaGetSymbolAddress((void**)&wsh,  g_wsh);
    cudaGetSymbolAddress((void**)&hhh,  g_hhh);
    cudaGetSymbolAddress((void**)&hw,   g_hw);
    cudaGetSymbolAddress((void**)&w,    g_w);

    // ---- streams/events (created once; EXACTLY 3 streams) ----
    static cudaStream_t sA = nullptr, s1 = nullptr, s2 = nullptr;
    static cudaEvent_t eFork, eT1a, eT1b, eTrW2, eSw, eCh1, eCh2, eDone;
    if (!sA) {
        cudaStreamCreateWithFlags(&sA, cudaStreamNonBlocking);
        cudaStreamCreateWithFlags(&s1, cudaStreamNonBlocking);
        cudaStreamCreateWithFlags(&s2, cudaStreamNonBlocking);
        cudaEventCreateWithFlags(&eFork, cudaEventDisableTiming);
        cudaEventCreateWithFlags(&eT1a,  cudaEventDisableTiming);
        cudaEventCreateWithFlags(&eT1b,  cudaEventDisableTiming);
        cudaEventCreateWithFlags(&eTrW2, cudaEventDisableTiming);
        cudaEventCreateWithFlags(&eSw,   cudaEventDisableTiming);
        cudaEventCreateWithFlags(&eCh1,  cudaEventDisableTiming);
        cudaEventCreateWithFlags(&eCh2,  cudaEventDisableTiming);
        cudaEventCreateWithFlags(&eDone, cudaEventDisableTiming);
    }

    const size_t WSTR = (size_t)KD * KD;
    const size_t ASTR = (size_t)Bq * KD;

    // fork from the harness's capture-origin stream
    cudaEventRecord(eFork, 0);
    cudaStreamWaitEvent(sA, eFork, 0);
    cudaStreamWaitEvent(s1, eFork, 0);
    cudaStreamWaitEvent(s2, eFork, 0);

    // -- main chain (sA): router -> gather
    router_kernel<<<(Bq * Nn * 32 + 255) / 256, 256, 0, sA>>>(x, emb, I);
    {
        size_t t4 = (size_t)Ee * Bq * KD / 4;
        gather_half_kernel<<<(unsigned)((t4 + 255) / 256), 256, 0, sA>>>(x, I, selh);
    }
    // s2: W1 transpose, first half (experts 0-3)
    transpose_half_kernel<<<dim3(KD / 64, KD / 64, 4), 256, 0, s2>>>(
        W1, W1h, KD, KD, WSTR, WSTR);
    cudaEventRecord(eT1a, s2);

    // fc1a (experts 0-3)  [4th kernel submission: ncu window]
    cudaStreamWaitEvent(sA, eT1a, 0);
    gemm_t1<<<dim3(Bq / 128, KD / 128, 4), 128, GEMM1_SMEM, sA>>>(
        selh, W1h, b1, nullptr, hh, nullptr,
        KD, KD, KD, 1, ASTR, WSTR, (size_t)KD, ASTR);

    // s2: W1 transpose, second half (experts 4-7)
    transpose_half_kernel<<<dim3(KD / 64, KD / 64, 4), 256, 0, s2>>>(
        W1 + 4 * WSTR, W1h + 4 * WSTR, KD, KD, WSTR, WSTR);
    cudaEventRecord(eT1b, s2);

    // fc1b (experts 4-7)
    cudaStreamWaitEvent(sA, eT1b, 0);
    gemm_t1<<<dim3(Bq / 128, KD / 128, 4), 128, GEMM1_SMEM, sA>>>(
        selh + 4 * ASTR, W1h + 4 * WSTR, b1 + 4 * KD, nullptr, hh + 4 * ASTR, nullptr,
        KD, KD, KD, 1, ASTR, WSTR, (size_t)KD, ASTR);

    // s1: the sum-weights chain
    {
        size_t t4 = (size_t)Bq * ND / 4;
        convert_half_kernel<<<(unsigned)((t4 + 255) / 256), 256, 0, s1>>>(x, xh, t4);
    }
    transpose_half_kernel<<<dim3(ND / 64, ND / 64, 1), 256, 0, s1>>>(
        swW1, sw1h, ND, ND, 0, 0);
    gemm_t1<<<dim3(Bq / 128, ND / 128, 1), 128, GEMM1_SMEM, s1>>>(
        xh, sw1h, swb1, hw, nullptr, nullptr,
        ND, ND, ND, 1, 0, 0, 0, 0);
    sw2_softmax_kernel<<<Bq, 256, 0, s1>>>(hw, swW2, swb2, w);
    cudaEventRecord(eSw, s1);

    // s2 continues: remaining weight transposes
    transpose_half_kernel<<<dim3(KD / 64, KD / 64, Ee), 256, 0, s2>>>(
        W2, W2h, KD, KD, WSTR, WSTR);
    cudaEventRecord(eTrW2, s2);
    transpose_half_kernel<<<dim3(KD / 64, KD / 64, 1), 256, 0, s2>>>(
        chW1, ch1h, KD, KD, 0, 0);
    cudaEventRecord(eCh1, s2);
    transpose_half_kernel<<<dim3(KD / 64, NCpad / 64, 1), 256, 0, s2>>>(
        chW2, ch2h, KD, NC, 0, 0);
    cudaEventRecord(eCh2, s2);

    // expert fc2 (batched z=8) -> single fp16 er
    cudaStreamWaitEvent(sA, eTrW2, 0);
    gemm_t1<<<dim3(Bq / 128, KD / 128, Ee), 128, GEMM1_SMEM, sA>>>(
        hh, W2h, b2, nullptr, erh, nullptr,
        KD, KD, KD, 0, ASTR, WSTR, (size_t)KD, ASTR);

    // join sw chain, weighted sum -> single fp16 ws
    cudaStreamWaitEvent(sA, eSw, 0);
    {
        size_t t4 = (size_t)Bq * KD / 4;
        wsum_half_kernel<<<(unsigned)((t4 + 255) / 256), 256, 0, sA>>>(erh, w, wsh);
    }

    // head fc1 -> single fp16 hh
    cudaStreamWaitEvent(sA, eCh1, 0);
    gemm_t1<<<dim3(Bq / 128, KD / 128, 1), 128, GEMM1_SMEM, sA>>>(
        wsh, ch1h, chb1, nullptr, hhh, nullptr,
        KD, KD, KD, 1, 0, 0, 0, 0);

    // head fc2 -> out
    cudaStreamWaitEvent(sA, eCh2, 0);
    gemm_t1<<<dim3(Bq / 128, NCpad / 128, 1), 128, GEMM1_SMEM, sA>>>(
        hhh, ch2h, chb2, out, nullptr, nullptr,
        KD, NC, NC, 0, 0, 0, 0, 0);

    // join everything back to the harness stream
    cudaEventRecord(eDone, sA);
    cudaStreamWaitEvent(0, eDone, 0);
}

// round 17
// speedup vs baseline: 1.0448x; 1.0448x over previous
#include <cuda_runtime.h>
#include <cuda_fp16.h>
#include <cstdint>
#include <cstddef>

// ---------------------------------------------------------------------------
// ExpertChoice via mma.sync fp16 GEMMs, all 1-term.
// R17: consolidate. t1 reverted to R15's 256-thread, 64x32-warp, 128x128 CTA
//      (R14/R16 proved 8 warps/SM collapses to ~46% tensor; 16 warps/SM is
//      required, and 64x32 is the bytes/MMA optimum under the 64-acc-reg cap).
//      Kept from R16: er single fp16 (measured 7.10e-4, passing).
// ---------------------------------------------------------------------------

#define Bq   1024
#define Nn   8
#define Dd   768
#define Ee   8
#define Kk   4
#define KD   3072
#define ND   6144
#define NC   1000
#define NCpad 1024

// ----- scratch (__device__ globals; no allocation allowed) ------------------
__device__ int   g_I[Bq * Nn * Kk];

__device__ __align__(16) __half g_W1h[(size_t)Ee * KD * KD];
__device__ __align__(16) __half g_W2h[(size_t)Ee * KD * KD];
__device__ __align__(16) __half g_sw1h[(size_t)ND * ND];
__device__ __align__(16) __half g_ch1h[(size_t)KD * KD];
__device__ __align__(16) __half g_ch2h[(size_t)NCpad * KD];

__device__ __align__(16) __half g_selh[(size_t)Ee * Bq * KD];
__device__ __align__(16) __half g_hh  [(size_t)Ee * Bq * KD];
__device__ __align__(16) __half g_erh[(size_t)Ee * Bq * KD];
__device__ __align__(16) __half g_xh[(size_t)Bq * ND];
__device__ float g_hw[(size_t)Bq * ND];
__device__ float g_w [Bq * Ee];
__device__ __align__(16) __half g_wsh[(size_t)Bq * KD];
__device__ __align__(16) __half g_hhh[(size_t)Bq * KD];

// ----- small helpers ---------------------------------------------------------
__device__ __forceinline__ float gelu_exact(float v) {
    return 0.5f * v * (1.0f + erff(v * 0.70710678118654752f));
}
__device__ __forceinline__ uint32_t smem_u32(const void* p) {
    uint32_t a;
    asm("{ .reg .u64 t; cvta.to.shared.u64 t, %1; cvt.u32.u64 %0, t; }" : "=r"(a) : "l"(p));
    return a;
}
__device__ __forceinline__ void cp_async16(uint32_t dst, const void* src) {
    asm volatile("cp.async.cg.shared.global [%0], [%1], 16;" :: "r"(dst), "l"(src));
}
__device__ __forceinline__ void cp_commit() {
    asm volatile("cp.async.commit_group;" ::: "memory");
}
template <int N>
__device__ __forceinline__ void cp_wait() {
    asm volatile("cp.async.wait_group %0;" :: "n"(N) : "memory");
}
__device__ __forceinline__ void ldsm_x4(uint32_t& r0, uint32_t& r1, uint32_t& r2,
                                        uint32_t& r3, uint32_t addr) {
    asm volatile("ldmatrix.sync.aligned.m8n8.x4.shared.b16 {%0,%1,%2,%3}, [%4];"
                 : "=r"(r0), "=r"(r1), "=r"(r2), "=r"(r3) : "r"(addr));
}
__device__ __forceinline__ void mma16816h(float* c, const uint32_t* a, const uint32_t* b) {
    asm volatile(
        "mma.sync.aligned.m16n8k16.row.col.f32.f16.f16.f32 "
        "{%0,%1,%2,%3}, {%4,%5,%6,%7}, {%8,%9}, {%0,%1,%2,%3};"
        : "+f"(c[0]), "+f"(c[1]), "+f"(c[2]), "+f"(c[3])
        : "r"(a[0]), "r"(a[1]), "r"(a[2]), "r"(a[3]), "r"(b[0]), "r"(b[1]));
}

// ----- router -----------------------------------------------------------------
__global__ void router_kernel(const float* __restrict__ x,
                              const float* __restrict__ emb,
                              int* __restrict__ I) {
    int gwarp = (blockIdx.x * blockDim.x + threadIdx.x) >> 5;
    int lane  = threadIdx.x & 31;
    if (gwarp >= Bq * Nn) return;
    int b = gwarp / Nn, n = gwarp % Nn;
    const float* xv = x + ((size_t)b * Nn + n) * Dd;
    float acc[Ee];
#pragma unroll
    for (int e = 0; e < Ee; e++) acc[e] = 0.f;
    for (int d = lane; d < Dd; d += 32) {
        float xd = xv[d];
#pragma unroll
        for (int e = 0; e < Ee; e++) acc[e] += xd * __ldg(&emb[e * Dd + d]);
    }
#pragma unroll
    for (int e = 0; e < Ee; e++)
#pragma unroll
        for (int off = 16; off; off >>= 1)
            acc[e] += __shfl_xor_sync(0xffffffffu, acc[e], off);
    if (lane == 0) {
        bool used[Ee] = {};
#pragma unroll
        for (int j = 0; j < Kk; j++) {
            int best = 0; float bv = -3.0e38f;
#pragma unroll
            for (int e = 0; e < Ee; e++)
                if (!used[e] && acc[e] > bv) { bv = acc[e]; best = e; }
            used[best] = true;
            I[((size_t)b * Nn + n) * Kk + j] = best;
        }
    }
}

// ----- gather -> single fp16 ----------------------------------------------------
__global__ void gather_half_kernel(const float* __restrict__ x,
                                   const int* __restrict__ I,
                                   __half* __restrict__ sh) {
    size_t idx = (size_t)blockIdx.x * blockDim.x + threadIdx.x;  // float4 index
    const size_t total = (size_t)Ee * Bq * KD / 4;
    if (idx >= total) return;
    int d4   = (int)(idx % (Dd / 4));
    size_t r = idx / (Dd / 4);
    int j = (int)(r % Kk); r /= Kk;
    int b = (int)(r % Bq);
    int e = (int)(r / Bq);
    int t = I[((size_t)b * Nn + e) * Kk + j];
    float4 v = reinterpret_cast<const float4*>(x)[((size_t)b * Nn + t) * (Dd / 4) + d4];
    __half2* oh = reinterpret_cast<__half2*>(sh + idx * 4);
    oh[0] = __halves2half2(__float2half_rn(v.x), __float2half_rn(v.y));
    oh[1] = __halves2half2(__float2half_rn(v.z), __float2half_rn(v.w));
}

__global__ void convert_half_kernel(const float* __restrict__ src,
                                    __half* __restrict__ dh, size_t n4) {
    size_t idx = (size_t)blockIdx.x * blockDim.x + threadIdx.x;
    if (idx >= n4) return;
    float4 v = reinterpret_cast<const float4*>(src)[idx];
    __half2* oh = reinterpret_cast<__half2*>(dh + idx * 4);
    oh[0] = __halves2half2(__float2half_rn(v.x), __float2half_rn(v.y));
    oh[1] = __halves2half2(__float2half_rn(v.z), __float2half_rn(v.w));
}

// ----- weight transpose -> single fp16 copy: Wt[n][k] = W[k][n] ----------------
__global__ __launch_bounds__(256)
void transpose_half_kernel(const float* __restrict__ W,
                           __half* __restrict__ Th,
                           int K, int N, size_t sW, size_t sT) {
    W  += (size_t)blockIdx.z * sW;
    Th += (size_t)blockIdx.z * sT;
    __shared__ float s[64][65];
    const int k0 = blockIdx.x * 64, n0 = blockIdx.y * 64;
    const int id = threadIdx.x;
#pragma unroll
    for (int it = 0; it < 16; it++) {
        int row = it * 4 + (id >> 6);
        int col = id & 63;
        int n = n0 + col;
        s[row][col] = (n < N) ? W[(size_t)(k0 + row) * N + n] : 0.f;
    }
    __syncthreads();
#pragma unroll
    for (int it = 0; it < 8; it++) {
        int n = it * 8 + (id >> 5);
        int c = id & 31;
        float v0 = s[2 * c][n], v1 = s[2 * c + 1][n];
        size_t o = ((size_t)(n0 + n) * K + k0 + 2 * c) >> 1;
        reinterpret_cast<__half2*>(Th)[o] =
            __halves2half2(__float2half_rn(v0), __float2half_rn(v1));
    }
}

// ----- GEMM config ---------------------------------------------------------------
#define BKc   32
#define ROW_B 64
#define TILE_B (128 * ROW_B)              // 8192 B per matrix tile
#define STAGE1_B (2 * TILE_B)             // A, B
#define NSTG1 4
#define GEMM1_SMEM (NSTG1 * STAGE1_B + 256)   // 65792 B; 2 CTAs/SM

// ----- 1-term GEMM: C = A*B^T + bias (R15-proven: 256 thr, 8 warps of 64x32,
//       128x128 CTA, 4-stage, one barrier per 2 K-steps) ------------------------
__global__ __launch_bounds__(256, 2)
void gemm_t1(const __half* __restrict__ Ah,
             const __half* __restrict__ Bh,
             const float* __restrict__ bias,
             float* __restrict__ Cf,
             __half* __restrict__ Ch,
             int K, int Nact, int ldC, int act,
             size_t strA, size_t strB, size_t strBias, size_t strC) {
    extern __shared__ char smem_raw[];
    uint32_t sb = (smem_u32(smem_raw) + 127u) & ~127u;

    const int tid  = threadIdx.x;
    const int wid  = tid >> 5;
    const int lane = tid & 31;
    const int wm = (wid >> 2) * 64;
    const int wn = (wid & 3) * 32;
    const int m0 = blockIdx.x * 128;
    const int n0 = blockIdx.y * 128;
    const int z  = blockIdx.z;

    Ah += (size_t)z * strA;
    Bh += (size_t)z * strB;
    bias += (size_t)z * strBias;
    if (Cf) Cf += (size_t)z * strC;
    if (Ch) Ch += (size_t)z * strC;

    const int row0 = tid >> 2;
    const int row1 = 64 + (tid >> 2);
    const int ck   = tid & 3;
    const size_t g0 = (size_t)row0 * K + ck * 8;
    const size_t g1 = (size_t)row1 * K + ck * 8;
    const uint32_t s0 = (uint32_t)(row0 * ROW_B + ((ck ^ ((row0 >> 1) & 3)) << 4));
    const uint32_t s1 = (uint32_t)(row1 * ROW_B + ((ck ^ ((row1 >> 1) & 3)) << 4));

    const __half* baseA = Ah + (size_t)m0 * K;
    const __half* baseB = Bh + (size_t)n0 * K;

    float acc[4][4][4];
#pragma unroll
    for (int a = 0; a < 4; a++)
#pragma unroll
        for (int b = 0; b < 4; b++)
#pragma unroll
            for (int c = 0; c < 4; c++) acc[a][b][c] = 0.f;

    auto load_stage = [&](int buf, int k0) {
        const uint32_t stg = sb + (uint32_t)buf * STAGE1_B;
        cp_async16(stg + s0, baseA + k0 + g0);
        cp_async16(stg + s1, baseA + k0 + g1);
        cp_async16(stg + TILE_B + s0, baseB + k0 + g0);
        cp_async16(stg + TILE_B + s1, baseB + k0 + g1);
    };

    const int nsteps = K / BKc;   // even for all call sites (96 or 192)
    load_stage(0, 0);
    cp_commit();
    load_stage(1, BKc);
    cp_commit();

    const int grp = lane >> 3;
    const int lr  = lane & 7;
    const int a_row = ((grp & 1) << 3) + lr;
    const int a_ck  = grp >> 1;
    const int b_row = ((grp >> 1) << 3) + lr;
    const int b_ck  = grp & 1;
    const int swz_a = ((wm + a_row) >> 1) & 3;
    const int swz_b = ((wn + b_row) >> 1) & 3;
    const uint32_t a_base = (uint32_t)(wm + a_row) * ROW_B;
    const uint32_t b_base = (uint32_t)(wn + b_row) * ROW_B;

    auto compute_step = [&](int bufidx) {
        const uint32_t stg = sb + (uint32_t)bufidx * STAGE1_B;
        const uint32_t sAh = stg;
        const uint32_t sBh = stg + TILE_B;
#pragma unroll
        for (int kk = 0; kk < 2; kk++) {
            const uint32_t a_coff = (uint32_t)(((kk * 2 + a_ck) ^ swz_a) << 4);
            const uint32_t b_coff = (uint32_t)(((kk * 2 + b_ck) ^ swz_b) << 4);
            uint32_t bh[4][2];
            {
                uint32_t boff = b_base + b_coff;
                ldsm_x4(bh[0][0], bh[0][1], bh[1][0], bh[1][1], sBh + boff);
                uint32_t boff2 = boff + 16 * ROW_B;
                ldsm_x4(bh[2][0], bh[2][1], bh[3][0], bh[3][1], sBh + boff2);
            }
            uint32_t ah[2][4];
            {
                uint32_t aoff = a_base + a_coff;
                ldsm_x4(ah[0][0], ah[0][1], ah[0][2], ah[0][3], sAh + aoff);
            }
#pragma unroll
            for (int mt = 0; mt < 4; mt++) {
                if (mt < 3) {
                    uint32_t aoff = a_base + (uint32_t)((mt + 1) * 16) * ROW_B + a_coff;
                    ldsm_x4(ah[(mt + 1) & 1][0], ah[(mt + 1) & 1][1],
                            ah[(mt + 1) & 1][2], ah[(mt + 1) & 1][3], sAh + aoff);
                }
#pragma unroll
                for (int nt = 0; nt < 4; nt++)
                    mma16816h(acc[mt][nt], ah[mt & 1], bh[nt]);
            }
        }
    };

    for (int s = 0; s < nsteps; s += 2) {
        cp_wait<0>();
        __syncthreads();
        if (s + 2 < nsteps) {
            load_stage((s + 2) & 3, (s + 2) * BKc);
            cp_commit();
            load_stage((s + 3) & 3, (s + 3) * BKc);
            cp_commit();
        }
        compute_step(s & 3);
        compute_step((s + 1) & 3);
    }

#pragma unroll
    for (int mt = 0; mt < 4; mt++) {
#pragma unroll
        for (int nt = 0; nt < 4; nt++) {
            int row = m0 + wm + mt * 16 + (lane >> 2);
            int col = n0 + wn + nt * 8 + ((lane & 3) << 1);
            if (col < Nact) {
                float bv0 = __ldg(&bias[col]);
                float bv1 = __ldg(&bias[col + 1]);
#pragma unroll
                for (int half_i = 0; half_i < 2; half_i++) {
                    int r = row + half_i * 8;
                    float v0 = acc[mt][nt][half_i * 2 + 0] + bv0;
                    float v1 = acc[mt][nt][half_i * 2 + 1] + bv1;
                    if (act) { v0 = gelu_exact(v0); v1 = gelu_exact(v1); }
                    size_t gidx = (size_t)r * ldC + col;
                    if (Cf) *reinterpret_cast<float2*>(Cf + gidx) = make_float2(v0, v1);
                    if (Ch)
                        *reinterpret_cast<__half2*>(Ch + gidx) =
                            __halves2half2(__float2half_rn(v0), __float2half_rn(v1));
                }
            }
        }
    }
}

// ----- sum-weights fc2 (N=8) + softmax (fp32) ----------------------------------
__global__ void sw2_softmax_kernel(const float* __restrict__ hw,
                                   const float* __restrict__ swW2,
                                   const float* __restrict__ swb2,
                                   float* __restrict__ w) {
    int b = blockIdx.x;
    int lane = threadIdx.x & 31, warp = threadIdx.x >> 5;
    float acc[Ee];
#pragma unroll
    for (int e = 0; e < Ee; e++) acc[e] = 0.f;
    const float* a = hw + (size_t)b * ND;
    for (int k = threadIdx.x; k < ND; k += 256) {
        float av = a[k];
#pragma unroll
        for (int e = 0; e < Ee; e++) acc[e] += av * __ldg(&swW2[(size_t)k * Ee + e]);
    }
#pragma unroll
    for (int e = 0; e < Ee; e++)
#pragma unroll
        for (int off = 16; off; off >>= 1)
            acc[e] += __shfl_xor_sync(0xffffffffu, acc[e], off);
    __shared__ float sh[8][Ee];
    if (lane == 0)
#pragma unroll
        for (int e = 0; e < Ee; e++) sh[warp][e] = acc[e];
    __syncthreads();
    if (threadIdx.x == 0) {
        float v[Ee]; float mx = -3.0e38f;
#pragma unroll
        for (int e = 0; e < Ee; e++) {
            float s = swb2[e];
            for (int wi = 0; wi < 8; wi++) s += sh[wi][e];
            v[e] = s; mx = fmaxf(mx, s);
        }
        float den = 0.f;
#pragma unroll
        for (int e = 0; e < Ee; e++) { v[e] = __expf(v[e] - mx); den += v[e]; }
        float inv = 1.0f / den;
#pragma unroll
        for (int e = 0; e < Ee; e++) w[b * Ee + e] = v[e] * inv;
    }
}

// ----- weighted sum over experts (single fp16 er) -> single fp16 ws -------------
__global__ void wsum_half_kernel(const __half* __restrict__ erh,
                                 const float* __restrict__ w,
                                 __half* __restrict__ wsh) {
    size_t idx = (size_t)blockIdx.x * blockDim.x + threadIdx.x;  // group of 4 elems
    const size_t total = (size_t)Bq * KD / 4;
    if (idx >= total) return;
    int b = (int)(idx / (KD / 4));
    float s0 = 0.f, s1 = 0.f, s2 = 0.f, s3 = 0.f;
#pragma unroll
    for (int e = 0; e < Ee; e++) {
        float we = __ldg(&w[b * Ee + e]);
        size_t o = (size_t)e * (Bq * KD / 4) + idx;
        uint2 hp = reinterpret_cast<const uint2*>(erh)[o];
        __half2 h01 = *reinterpret_cast<__half2*>(&hp.x);
        __half2 h23 = *reinterpret_cast<__half2*>(&hp.y);
        s0 += we * __half2float(h01.x);
        s1 += we * __half2float(h01.y);
        s2 += we * __half2float(h23.x);
        s3 += we * __half2float(h23.y);
    }
    __half2* oh = reinterpret_cast<__half2*>(wsh + idx * 4);
    oh[0] = __halves2half2(__float2half_rn(s0), __float2half_rn(s1));
    oh[1] = __halves2half2(__float2half_rn(s2), __float2half_rn(s3));
}

// ------------------------------------------------------------------------------
extern "C" void kernel_launch(void* const* d_in, const int* in_sizes, int n_in,
                              void* d_out, int out_size) {
    const float* x    = (const float*)d_in[0];
    const float* emb  = (const float*)d_in[1];
    const float* W1   = (const float*)d_in[2];
    const float* b1   = (const float*)d_in[3];
    const float* W2   = (const float*)d_in[4];
    const float* b2   = (const float*)d_in[5];
    const float* swW1 = (const float*)d_in[6];
    const float* swb1 = (const float*)d_in[7];
    const float* swW2 = (const float*)d_in[8];
    const float* swb2 = (const float*)d_in[9];
    const float* chW1 = (const float*)d_in[10];
    const float* chb1 = (const float*)d_in[11];
    const float* chW2 = (const float*)d_in[12];
    const float* chb2 = (const float*)d_in[13];
    float* out = (float*)d_out;

    cudaFuncSetAttribute(gemm_t1, cudaFuncAttributeMaxDynamicSharedMemorySize, GEMM1_SMEM);

    int* I;
    __half *W1h, *W2h, *sw1h, *ch1h, *ch2h;
    __half *selh, *hh, *erh, *xh, *wsh, *hhh;
    float *hw, *w;
    cudaGetSymbolAddress((void**)&I,    g_I);
    cudaGetSymbolAddress((void**)&W1h,  g_W1h);
    cudaGetSymbolAddress((void**)&W2h,  g_W2h);
    cudaGetSymbolAddress((void**)&sw1h, g_sw1h);
    cudaGetSymbolAddress((void**)&ch1h, g_ch1h);
    cudaGetSymbolAddress((void**)&ch2h, g_ch2h);
    cudaGetSymbolAddress((void**)&selh, g_selh);
    cudaGetSymbolAddress((void**)&hh,   g_hh);
    cudaGetSymbolAddress((void**)&erh,  g_erh);
    cudaGetSymbolAddress((void**)&xh,   g_xh);
    cudaGetSymbolAddress((void**)&wsh,  g_wsh);
    cudaGetSymbolAddress((void**)&hhh,  g_hhh);
    cudaGetSymbolAddress((void**)&hw,   g_hw);
    cudaGetSymbolAddress((void**)&w,    g_w);

    // ---- streams/events (created once; EXACTLY 3 streams) ----
    static cudaStream_t sA = nullptr, s1 = nullptr, s2 = nullptr;
    static cudaEvent_t eFork, eT1a, eT1b, eTrW2, eSw, eCh1, eCh2, eDone;
    if (!sA) {
        cudaStreamCreateWithFlags(&sA, cudaStreamNonBlocking);
        cudaStreamCreateWithFlags(&s1, cudaStreamNonBlocking);
        cudaStreamCreateWithFlags(&s2, cudaStreamNonBlocking);
        cudaEventCreateWithFlags(&eFork, cudaEventDisableTiming);
        cudaEventCreateWithFlags(&eT1a,  cudaEventDisableTiming);
        cudaEventCreateWithFlags(&eT1b,  cudaEventDisableTiming);
        cudaEventCreateWithFlags(&eTrW2, cudaEventDisableTiming);
        cudaEventCreateWithFlags(&eSw,   cudaEventDisableTiming);
        cudaEventCreateWithFlags(&eCh1,  cudaEventDisableTiming);
        cudaEventCreateWithFlags(&eCh2,  cudaEventDisableTiming);
        cudaEventCreateWithFlags(&eDone, cudaEventDisableTiming);
    }

    const size_t WSTR = (size_t)KD * KD;
    const size_t ASTR = (size_t)Bq * KD;

    // fork from the harness's capture-origin stream
    cudaEventRecord(eFork, 0);
    cudaStreamWaitEvent(sA, eFork, 0);
    cudaStreamWaitEvent(s1, eFork, 0);
    cudaStreamWaitEvent(s2, eFork, 0);

    // -- main chain (sA): router -> gather
    router_kernel<<<(Bq * Nn * 32 + 255) / 256, 256, 0, sA>>>(x, emb, I);
    {
        size_t t4 = (size_t)Ee * Bq * KD / 4;
        gather_half_kernel<<<(unsigned)((t4 + 255) / 256), 256, 0, sA>>>(x, I, selh);
    }
    // s2: W1 transpose, first half (experts 0-3)
    transpose_half_kernel<<<dim3(KD / 64, KD / 64, 4), 256, 0, s2>>>(
        W1, W1h, KD, KD, WSTR, WSTR);
    cudaEventRecord(eT1a, s2);

    // fc1a (experts 0-3)  [4th kernel submission: ncu window]
    cudaStreamWaitEvent(sA, eT1a, 0);
    gemm_t1<<<dim3(Bq / 128, KD / 128, 4), 256, GEMM1_SMEM, sA>>>(
        selh, W1h, b1, nullptr, hh,
        KD, KD, KD, 1, ASTR, WSTR, (size_t)KD, ASTR);

    // s2: W1 transpose, second half (experts 4-7)
    transpose_half_kernel<<<dim3(KD / 64, KD / 64, 4), 256, 0, s2>>>(
        W1 + 4 * WSTR, W1h + 4 * WSTR, KD, KD, WSTR, WSTR);
    cudaEventRecord(eT1b, s2);

    // fc1b (experts 4-7)
    cudaStreamWaitEvent(sA, eT1b, 0);
    gemm_t1<<<dim3(Bq / 128, KD / 128, 4), 256, GEMM1_SMEM, sA>>>(
        selh + 4 * ASTR, W1h + 4 * WSTR, b1 + 4 * KD, nullptr, hh + 4 * ASTR,
        KD, KD, KD, 1, ASTR, WSTR, (size_t)KD, ASTR);

    // s1: the sum-weights chain
    {
        size_t t4 = (size_t)Bq * ND / 4;
        convert_half_kernel<<<(unsigned)((t4 + 255) / 256), 256, 0, s1>>>(x, xh, t4);
    }
    transpose_half_kernel<<<dim3(ND / 64, ND / 64, 1), 256, 0, s1>>>(
        swW1, sw1h, ND, ND, 0, 0);
    gemm_t1<<<dim3(Bq / 128, ND / 128, 1), 256, GEMM1_SMEM, s1>>>(
        xh, sw1h, swb1, hw, nullptr,
        ND, ND, ND, 1, 0, 0, 0, 0);
    sw2_softmax_kernel<<<Bq, 256, 0, s1>>>(hw, swW2, swb2, w);
    cudaEventRecord(eSw, s1);

    // s2 continues: remaining weight transposes
    transpose_half_kernel<<<dim3(KD / 64, KD / 64, Ee), 256, 0, s2>>>(
        W2, W2h, KD, KD, WSTR, WSTR);
    cudaEventRecord(eTrW2, s2);
    transpose_half_kernel<<<dim3(KD / 64, KD / 64, 1), 256, 0, s2>>>(
        chW1, ch1h, KD, KD, 0, 0);
    cudaEventRecord(eCh1, s2);
    transpose_half_kernel<<<dim3(KD / 64, NCpad / 64, 1), 256, 0, s2>>>(
        chW2, ch2h, KD, NC, 0, 0);
    cudaEventRecord(eCh2, s2);

    // expert fc2 (batched z=8) -> single fp16 er
    cudaStreamWaitEvent(sA, eTrW2, 0);
    gemm_t1<<<dim3(Bq / 128, KD / 128, Ee), 256, GEMM1_SMEM, sA>>>(
        hh, W2h, b2, nullptr, erh,
        KD, KD, KD, 0, ASTR, WSTR, (size_t)KD, ASTR);

    // join sw chain, weighted sum -> single fp16 ws
    cudaStreamWaitEvent(sA, eSw, 0);
    {
        size_t t4 = (size_t)Bq * KD / 4;
        wsum_half_kernel<<<(unsigned)((t4 + 255) / 256), 256, 0, sA>>>(erh, w, wsh);
    }

    // head fc1 -> single fp16 hh
    cudaStreamWaitEvent(sA, eCh1, 0);
    gemm_t1<<<dim3(Bq / 128, KD / 128, 1), 256, GEMM1_SMEM, sA>>>(
        wsh, ch1h, chb1, nullptr, hhh,
        KD, KD, KD, 1, 0, 0, 0, 0);

    // head fc2 -> out
    cudaStreamWaitEvent(sA, eCh2, 0);
    gemm_t1<<<dim3(Bq / 128, NCpad / 128, 1), 256, GEMM1_SMEM, sA>>>(
        hhh, ch2h, chb2, out, nullptr,
        KD, NC, NC, 0, 0, 0, 0, 0);

    // join everything back to the harness stream
    cudaEventRecord(eDone, sA);
    cudaStreamWaitEvent(0, eDone, 0);
}